// round 2
// baseline (speedup 1.0000x reference)
#include <cuda_runtime.h>
#include <cuda_bf16.h>

// Fractal2DDiff: differentiable decision-tree routing over a 1024x1024 grid.
// B=1M points, N=64 nodes, C=16 classes, depth=10.
//
// Math: per point, left[n] = (1-dir[n])*sig(sp[n]-x) + dir[n]*sig(sp[n]-y)
//       p <- (p*left)@L + (p*(1-left))@R   (x depth), then out = p @ softmax(class_logits)
// L,R are row-stochastic => sum(p) is invariant => per-step normalization is a no-op;
// we normalize once at the end.
//
// Layout: lane = point. L,R,CP live in shared and are read via broadcast LDS.128
// (ulonglong2 -> f32x2 register pairs). Per-point state p[64], left[64] lives in
// shared laid out [n][tid] (conflict-free, each lane touches only its own column,
// so no intra-iteration sync is needed). MACs use Blackwell packed fma.rn.f32x2
// (2x fp32 throughput vs scalar FFMA).

#define N_NODES   64
#define N_CLASSES 16
#define TPB       128

typedef unsigned long long u64;

__device__ float g_L[N_NODES * N_NODES];
__device__ float g_R[N_NODES * N_NODES];
__device__ float g_CP[N_NODES * N_CLASSES];
__device__ float g_dirs[N_NODES];

// ---------------------------------------------------------------------------
// Setup: sigmoid(dir logits), softmax rows of child_selection_logits (L, R),
// softmax rows of class_logits (CP). One tiny block; accurate expf.
// ---------------------------------------------------------------------------
__global__ void fractal_setup_kernel(const float* __restrict__ dir_logits,
                                     const float* __restrict__ class_logits,
                                     const float* __restrict__ child_logits) {
    int t = threadIdx.x;
    if (t >= N_NODES) return;

    g_dirs[t] = 1.0f / (1.0f + expf(-dir_logits[t]));

    // L row t and R row t: child_logits layout [N][2][N]
    const float* lrow = child_logits + (size_t)t * 2 * N_NODES;
    const float* rrow = lrow + N_NODES;

    {
        float m = -1e30f;
        for (int i = 0; i < N_NODES; i++) m = fmaxf(m, lrow[i]);
        float s = 0.0f;
        for (int i = 0; i < N_NODES; i++) s += expf(lrow[i] - m);
        float inv = 1.0f / s;
        for (int i = 0; i < N_NODES; i++) g_L[t * N_NODES + i] = expf(lrow[i] - m) * inv;
    }
    {
        float m = -1e30f;
        for (int i = 0; i < N_NODES; i++) m = fmaxf(m, rrow[i]);
        float s = 0.0f;
        for (int i = 0; i < N_NODES; i++) s += expf(rrow[i] - m);
        float inv = 1.0f / s;
        for (int i = 0; i < N_NODES; i++) g_R[t * N_NODES + i] = expf(rrow[i] - m) * inv;
    }
    {
        const float* crow = class_logits + t * N_CLASSES;
        float m = -1e30f;
        for (int i = 0; i < N_CLASSES; i++) m = fmaxf(m, crow[i]);
        float s = 0.0f;
        for (int i = 0; i < N_CLASSES; i++) s += expf(crow[i] - m);
        float inv = 1.0f / s;
        for (int i = 0; i < N_CLASSES; i++) g_CP[t * N_CLASSES + i] = expf(crow[i] - m) * inv;
    }
}

// Packed f32x2 helpers (Blackwell sm_103a).
#define FMA2(acc, a, b) \
    asm("fma.rn.f32x2 %0, %1, %2, %0;" : "+l"(acc) : "l"(a), "l"(b))
#define PACK_DUP(d, s) \
    asm("mov.b64 %0, {%1, %1};" : "=l"(d) : "f"(s))
#define UNPACK2(lo, hi, v) \
    asm("mov.b64 {%0, %1}, %2;" : "=f"(lo), "=f"(hi) : "l"(v))

__device__ __forceinline__ int decode_depth(const void* mdp) {
    int v = *reinterpret_cast<const int*>(mdp);
    if (v >= 1 && v <= 1000) return v;
    float f = __int_as_float(v);
    if (f >= 1.0f && f <= 1000.0f) return (int)f;
    return 10;
}

// Shared memory floats:
//   Ls 4096 | Rs 4096 | CPs 1024 | SPs 64 | DIRs 64 | Pm 64*TPB | Lf 64*TPB
#define SMEM_FLOATS (4096 + 4096 + 1024 + 64 + 64 + 64 * TPB + 64 * TPB)
#define SMEM_BYTES  (SMEM_FLOATS * 4)

__global__ __launch_bounds__(TPB, 2)
void fractal_main_kernel(const float* __restrict__ x_pos,
                         const float* __restrict__ y_pos,
                         const float* __restrict__ sp,
                         const void*  __restrict__ max_depth_ptr,
                         float* __restrict__ out,
                         int B) {
    extern __shared__ float sm[];
    float* Ls   = sm;                 // [64][64]
    float* Rs   = Ls + 4096;          // [64][64]
    float* CPs  = Rs + 4096;          // [64][16]
    float* SPs  = CPs + 1024;         // [64]
    float* DIRs = SPs + 64;           // [64]
    float* Pm   = DIRs + 64;          // [64][TPB]  p state, column-per-thread
    float* Lf   = Pm + 64 * TPB;      // [64][TPB]  left, column-per-thread

    const int tid = threadIdx.x;

    // Cooperative table load (global -> shared)
    for (int i = tid; i < 4096; i += TPB) { Ls[i] = g_L[i]; Rs[i] = g_R[i]; }
    for (int i = tid; i < 1024; i += TPB) CPs[i] = g_CP[i];
    if (tid < N_NODES) { SPs[tid] = sp[tid]; DIRs[tid] = g_dirs[tid]; }
    __syncthreads();

    const long long gid = (long long)blockIdx.x * TPB + tid;
    if (gid >= B) return;

    const int md = decode_depth(max_depth_ptr);
    const float x = x_pos[gid];
    const float y = y_pos[gid];

    // Precompute left[n] and init p (only this thread touches its column -> no sync)
    #pragma unroll 4
    for (int n = 0; n < N_NODES; ++n) {
        float s = SPs[n], d = DIRs[n];
        float hl = 1.0f / (1.0f + __expf(x - s));   // sigmoid(s - x)
        float vl = 1.0f / (1.0f + __expf(y - s));   // sigmoid(s - y)
        Lf[n * TPB + tid] = (1.0f - d) * hl + d * vl;
        Pm[n * TPB + tid] = (n == 0) ? 1.0f : 0.0f;
    }

    // Depth iterations. Sum of p is invariant (L,R row-stochastic) -> no per-step
    // normalization needed.
    for (int it = 0; it < md; ++it) {
        u64 nx[32];
        #pragma unroll
        for (int j = 0; j < 32; j++) nx[j] = 0ull;

        #pragma unroll 1
        for (int n = 0; n < N_NODES; ++n) {
            float p  = Pm[n * TPB + tid];
            float lf = Lf[n * TPB + tid];
            float a = p * lf;
            float b = p - a;
            u64 a2, b2;
            PACK_DUP(a2, a);
            PACK_DUP(b2, b);
            const ulonglong2* Lr = reinterpret_cast<const ulonglong2*>(Ls + n * 64);
            const ulonglong2* Rr = reinterpret_cast<const ulonglong2*>(Rs + n * 64);
            #pragma unroll
            for (int k = 0; k < 16; k++) {
                ulonglong2 l = Lr[k];   // L[n][4k..4k+3] as two f32x2 pairs (broadcast LDS.128)
                ulonglong2 r = Rr[k];
                FMA2(nx[2 * k],     a2, l.x);
                FMA2(nx[2 * k],     b2, r.x);
                FMA2(nx[2 * k + 1], a2, l.y);
                FMA2(nx[2 * k + 1], b2, r.y);
            }
        }

        #pragma unroll
        for (int j = 0; j < 32; j++) {
            float lo, hi;
            UNPACK2(lo, hi, nx[j]);
            Pm[(2 * j)     * TPB + tid] = lo;
            Pm[(2 * j + 1) * TPB + tid] = hi;
        }
    }

    // Final: class_probs = (p / max(sum(p), eps)) @ CP
    u64 ac[8];
    #pragma unroll
    for (int j = 0; j < 8; j++) ac[j] = 0ull;
    float sum = 0.0f;

    #pragma unroll 1
    for (int n = 0; n < N_NODES; ++n) {
        float p = Pm[n * TPB + tid];
        sum += p;
        u64 p2;
        PACK_DUP(p2, p);
        const ulonglong2* Cr = reinterpret_cast<const ulonglong2*>(CPs + n * N_CLASSES);
        #pragma unroll
        for (int k = 0; k < 4; k++) {
            ulonglong2 c = Cr[k];
            FMA2(ac[2 * k],     p2, c.x);
            FMA2(ac[2 * k + 1], p2, c.y);
        }
    }

    float inv = 1.0f / fmaxf(sum, 1e-10f);
    float4* o4 = reinterpret_cast<float4*>(out + gid * N_CLASSES);
    #pragma unroll
    for (int k = 0; k < 4; k++) {
        float lo, hi, lo2, hi2;
        UNPACK2(lo, hi, ac[2 * k]);
        UNPACK2(lo2, hi2, ac[2 * k + 1]);
        float4 v;
        v.x = lo * inv; v.y = hi * inv; v.z = lo2 * inv; v.w = hi2 * inv;
        o4[k] = v;
    }
}

// ---------------------------------------------------------------------------
// Harness entry point.
// Inputs (metadata order): x_pos[B], y_pos[B], split_points[64],
// split_directions_logits[64], class_logits[64*16], child_selection_logits[64*2*64],
// max_depth[1]. Output: float32 [B*16].
// ---------------------------------------------------------------------------
extern "C" void kernel_launch(void* const* d_in, const int* in_sizes, int n_in,
                              void* d_out, int out_size) {
    const float* x_pos = (const float*)d_in[0];
    const float* y_pos = (const float*)d_in[1];
    const float* sp    = (const float*)d_in[2];
    const float* dirl  = (const float*)d_in[3];
    const float* cls   = (const float*)d_in[4];
    const float* child = (const float*)d_in[5];
    const void*  mdp   = d_in[6];
    float* out = (float*)d_out;

    int B = in_sizes[0];

    cudaFuncSetAttribute(fractal_main_kernel,
                         cudaFuncAttributeMaxDynamicSharedMemorySize, SMEM_BYTES);

    fractal_setup_kernel<<<1, 64>>>(dirl, cls, child);

    int grid = (B + TPB - 1) / TPB;
    fractal_main_kernel<<<grid, TPB, SMEM_BYTES>>>(x_pos, y_pos, sp, mdp, out, B);
}

// round 3
// speedup vs baseline: 1.3180x; 1.3180x over previous
#include <cuda_runtime.h>
#include <cuda_bf16.h>

// Fractal2DDiff — register-tiled warp micro-GEMM version.
//
// p <- (p*left)@L + (p*(1-left))@R  ==  (p*left)@(L-R) + p@R
// L,R row-stochastic => sum(p) invariant => normalize once at end.
//
// Each warp owns 32 points. Each lane owns an 8pt x 8col register tile
// (64 fp32 accumulators as 32 f32x2 regs). Per node n a lane loads:
//   - D,R table values for its 8 cols (4x LDS.128, distributed across lanes)
//   - p,left for its 8 pts      (4x LDS.128, 8-way broadcast chunks)
// and performs 64 packed fma.rn.f32x2 -> 128 MACs. LDS bytes per MAC drop
// ~5x vs the broadcast kernel; FMA pipe becomes the bottleneck.

#define N_NODES   64
#define N_CLASSES 16
#define TPB       128
#define WARPS     4
#define PSTRIDE   36   // floats per p/left row (32 + pad, keeps reads conflict-free)

typedef unsigned long long u64;

__device__ float g_D[N_NODES * N_NODES];   // L - R
__device__ float g_R[N_NODES * N_NODES];   // R
__device__ float g_CP[N_NODES * N_CLASSES];
__device__ float g_dirs[N_NODES];

// ---------------------------------------------------------------------------
__global__ void fractal_setup_kernel(const float* __restrict__ dir_logits,
                                     const float* __restrict__ class_logits,
                                     const float* __restrict__ child_logits) {
    int t = threadIdx.x;
    if (t >= N_NODES) return;

    g_dirs[t] = 1.0f / (1.0f + expf(-dir_logits[t]));

    const float* lrow = child_logits + (size_t)t * 2 * N_NODES;
    const float* rrow = lrow + N_NODES;

    float Lv[N_NODES], Rv[N_NODES];
    {
        float m = -1e30f;
        for (int i = 0; i < N_NODES; i++) m = fmaxf(m, lrow[i]);
        float s = 0.0f;
        for (int i = 0; i < N_NODES; i++) s += expf(lrow[i] - m);
        float inv = 1.0f / s;
        for (int i = 0; i < N_NODES; i++) Lv[i] = expf(lrow[i] - m) * inv;
    }
    {
        float m = -1e30f;
        for (int i = 0; i < N_NODES; i++) m = fmaxf(m, rrow[i]);
        float s = 0.0f;
        for (int i = 0; i < N_NODES; i++) s += expf(rrow[i] - m);
        float inv = 1.0f / s;
        for (int i = 0; i < N_NODES; i++) Rv[i] = expf(rrow[i] - m) * inv;
    }
    for (int i = 0; i < N_NODES; i++) {
        g_D[t * N_NODES + i] = Lv[i] - Rv[i];
        g_R[t * N_NODES + i] = Rv[i];
    }
    {
        const float* crow = class_logits + t * N_CLASSES;
        float m = -1e30f;
        for (int i = 0; i < N_CLASSES; i++) m = fmaxf(m, crow[i]);
        float s = 0.0f;
        for (int i = 0; i < N_CLASSES; i++) s += expf(crow[i] - m);
        float inv = 1.0f / s;
        for (int i = 0; i < N_CLASSES; i++) g_CP[t * N_CLASSES + i] = expf(crow[i] - m) * inv;
    }
}

// Packed f32x2 helpers (Blackwell sm_103a).
#define FMA2(acc, a, b) \
    asm("fma.rn.f32x2 %0, %1, %2, %0;" : "+l"(acc) : "l"(a), "l"(b))
#define MUL2(d, a, b) \
    asm("mul.rn.f32x2 %0, %1, %2;" : "=l"(d) : "l"(a), "l"(b))
#define PACK_DUP(d, s) \
    asm("mov.b64 %0, {%1, %1};" : "=l"(d) : "f"(s))
#define UNPACK2(lo, hi, v) \
    asm("mov.b64 {%0, %1}, %2;" : "=f"(lo), "=f"(hi) : "l"(v))

__device__ __forceinline__ int decode_depth(const void* mdp) {
    int v = *reinterpret_cast<const int*>(mdp);
    if (v >= 1 && v <= 1000) return v;
    float f = __int_as_float(v);
    if (f >= 1.0f && f <= 1000.0f) return (int)f;
    return 10;
}

// Shared memory (floats):
//   Ds 4096 | Rs 4096 | CPs 1024 | SPs 64 | DIRs 64 |
//   P  WARPS*64*PSTRIDE | Lf WARPS*64*PSTRIDE
#define SMEM_FLOATS (4096 + 4096 + 1024 + 64 + 64 + 2 * WARPS * N_NODES * PSTRIDE)
#define SMEM_BYTES  (SMEM_FLOATS * 4)

__global__ __launch_bounds__(TPB, 2)
void fractal_main_kernel(const float* __restrict__ x_pos,
                         const float* __restrict__ y_pos,
                         const float* __restrict__ sp,
                         const void*  __restrict__ max_depth_ptr,
                         float* __restrict__ out,
                         int B) {
    extern __shared__ float sm[];
    float* Ds    = sm;                                    // [64][64]
    float* Rs    = Ds + 4096;                             // [64][64]
    float* CPs   = Rs + 4096;                             // [64][16]
    float* SPs   = CPs + 1024;                            // [64]
    float* DIRs  = SPs + 64;                              // [64]
    float* Pbase = DIRs + 64;                             // [WARPS][64][PSTRIDE]
    float* Lfbase = Pbase + WARPS * N_NODES * PSTRIDE;

    const int tid  = threadIdx.x;
    const int wid  = tid >> 5;
    const int lane = tid & 31;
    const int cg   = lane & 7;    // col group (8 cols: 4cg..4cg+3 and 32+4cg..+3)
    const int pg   = lane >> 3;   // point group (8 pts: 8pg..8pg+7)

    // Cooperative table load
    for (int i = tid; i < 4096; i += TPB) { Ds[i] = g_D[i]; Rs[i] = g_R[i]; }
    for (int i = tid; i < 1024; i += TPB) CPs[i] = g_CP[i];
    if (tid < N_NODES) { SPs[tid] = sp[tid]; DIRs[tid] = g_dirs[tid]; }
    __syncthreads();

    float* Pw  = Pbase  + wid * N_NODES * PSTRIDE;
    float* Lfw = Lfbase + wid * N_NODES * PSTRIDE;

    const long long warp_pt0 = (long long)blockIdx.x * TPB + wid * 32;
    const long long my_pt    = warp_pt0 + lane;
    const bool in_range = (my_pt < B);

    const int md = decode_depth(max_depth_ptr);
    const float x = in_range ? x_pos[my_pt] : 0.0f;
    const float y = in_range ? y_pos[my_pt] : 0.0f;

    // Init p and left: lane handles local point `lane` across all nodes.
    // Writes addr 36n+lane -> bank (4n+lane)%32: conflict-free per instruction.
    #pragma unroll 4
    for (int n = 0; n < N_NODES; ++n) {
        float s = SPs[n], d = DIRs[n];
        float hl = 1.0f / (1.0f + __expf(x - s));   // sigmoid(s - x)
        float vl = 1.0f / (1.0f + __expf(y - s));   // sigmoid(s - y)
        Lfw[n * PSTRIDE + lane] = (1.0f - d) * hl + d * vl;
        Pw[n * PSTRIDE + lane]  = (n == 0) ? 1.0f : 0.0f;
    }
    __syncwarp();

    // Depth loop: acc[c][q] = f32x2 over point-pairs q (8 pts), c over 8 cols.
    for (int it = 0; it < md; ++it) {
        u64 acc[8][4];
        #pragma unroll
        for (int c = 0; c < 8; c++)
            #pragma unroll
            for (int q = 0; q < 4; q++) acc[c][q] = 0ull;

        #pragma unroll 2
        for (int n = 0; n < N_NODES; ++n) {
            const float* drow = Ds + n * 64;
            const float* rrow = Rs + n * 64;
            // Distributed table loads: 8 contiguous 16B chunks across cg -> conflict-free
            ulonglong2 dlo = *reinterpret_cast<const ulonglong2*>(drow + 4 * cg);
            ulonglong2 dhi = *reinterpret_cast<const ulonglong2*>(drow + 32 + 4 * cg);
            ulonglong2 rlo = *reinterpret_cast<const ulonglong2*>(rrow + 4 * cg);
            ulonglong2 rhi = *reinterpret_cast<const ulonglong2*>(rrow + 32 + 4 * cg);

            const float* prow = Pw  + n * PSTRIDE + 8 * pg;
            const float* lrow = Lfw + n * PSTRIDE + 8 * pg;
            ulonglong2 pA = *reinterpret_cast<const ulonglong2*>(prow);
            ulonglong2 pB = *reinterpret_cast<const ulonglong2*>(prow + 4);
            ulonglong2 lA = *reinterpret_cast<const ulonglong2*>(lrow);
            ulonglong2 lB = *reinterpret_cast<const ulonglong2*>(lrow + 4);

            u64 p2[4] = { pA.x, pA.y, pB.x, pB.y };
            u64 l2[4] = { lA.x, lA.y, lB.x, lB.y };
            u64 a2[4];
            #pragma unroll
            for (int q = 0; q < 4; q++) MUL2(a2[q], p2[q], l2[q]);   // a = p*left

            // Broadcast-dup table scalars into f32x2
            float dsc[8], rsc[8];
            UNPACK2(dsc[0], dsc[1], dlo.x); UNPACK2(dsc[2], dsc[3], dlo.y);
            UNPACK2(dsc[4], dsc[5], dhi.x); UNPACK2(dsc[6], dsc[7], dhi.y);
            UNPACK2(rsc[0], rsc[1], rlo.x); UNPACK2(rsc[2], rsc[3], rlo.y);
            UNPACK2(rsc[4], rsc[5], rhi.x); UNPACK2(rsc[6], rsc[7], rhi.y);

            #pragma unroll
            for (int c = 0; c < 8; c++) {
                u64 dd, rr;
                PACK_DUP(dd, dsc[c]);
                PACK_DUP(rr, rsc[c]);
                #pragma unroll
                for (int q = 0; q < 4; q++) {
                    FMA2(acc[c][q], a2[q], dd);   // a @ (L-R)
                    FMA2(acc[c][q], p2[q], rr);   // p @ R
                }
            }
        }

        __syncwarp();   // all lanes done reading P before overwrite

        // Writeback: P[col][8pg + 2q..] = acc. STS.64, ~4-way conflict (ok).
        #pragma unroll
        for (int c = 0; c < 8; c++) {
            int col = (c < 4) ? (4 * cg + c) : (28 + 4 * cg + c);  // {4cg..}U{32+4cg..}
            u64* dst = reinterpret_cast<u64*>(Pw + col * PSTRIDE + 8 * pg);
            #pragma unroll
            for (int q = 0; q < 4; q++) dst[q] = acc[c][q];
        }
        __syncwarp();
    }

    // Final: out = (p / max(sum p, eps)) @ CP. Lane handles its own point.
    if (in_range) {
        float sum = 0.0f;
        u64 o2[8];
        #pragma unroll
        for (int k = 0; k < 8; k++) o2[k] = 0ull;

        #pragma unroll 4
        for (int n = 0; n < N_NODES; ++n) {
            float pv = Pw[n * PSTRIDE + lane];
            sum += pv;
            u64 pv2;
            PACK_DUP(pv2, pv);
            const ulonglong2* crow = reinterpret_cast<const ulonglong2*>(CPs + n * N_CLASSES);
            #pragma unroll
            for (int k = 0; k < 4; k++) {
                ulonglong2 cv = crow[k];
                FMA2(o2[2 * k],     pv2, cv.x);
                FMA2(o2[2 * k + 1], pv2, cv.y);
            }
        }

        float inv = 1.0f / fmaxf(sum, 1e-10f);
        float4* o4 = reinterpret_cast<float4*>(out + my_pt * N_CLASSES);
        #pragma unroll
        for (int k = 0; k < 4; k++) {
            float a0, a1, a2f, a3;
            UNPACK2(a0, a1, o2[2 * k]);
            UNPACK2(a2f, a3, o2[2 * k + 1]);
            float4 v;
            v.x = a0 * inv; v.y = a1 * inv; v.z = a2f * inv; v.w = a3 * inv;
            o4[k] = v;
        }
    }
}

// ---------------------------------------------------------------------------
extern "C" void kernel_launch(void* const* d_in, const int* in_sizes, int n_in,
                              void* d_out, int out_size) {
    const float* x_pos = (const float*)d_in[0];
    const float* y_pos = (const float*)d_in[1];
    const float* sp    = (const float*)d_in[2];
    const float* dirl  = (const float*)d_in[3];
    const float* cls   = (const float*)d_in[4];
    const float* child = (const float*)d_in[5];
    const void*  mdp   = d_in[6];
    float* out = (float*)d_out;

    int B = in_sizes[0];

    cudaFuncSetAttribute(fractal_main_kernel,
                         cudaFuncAttributeMaxDynamicSharedMemorySize, SMEM_BYTES);

    fractal_setup_kernel<<<1, 64>>>(dirl, cls, child);

    int grid = (B + TPB - 1) / TPB;
    fractal_main_kernel<<<grid, TPB, SMEM_BYTES>>>(x_pos, y_pos, sp, mdp, out, B);
}

// round 4
// speedup vs baseline: 1.3208x; 1.0022x over previous
#include <cuda_runtime.h>
#include <cuda_bf16.h>

// Fractal2DDiff — register-tiled warp micro-GEMM version.
//
// p <- (p*left)@L + (p*(1-left))@R  ==  (p*left)@(L-R) + p@R
// L,R row-stochastic => sum(p) invariant => normalize once at end.
//
// Each warp owns 32 points. Each lane owns an 8pt x 8col register tile
// (64 fp32 accumulators as 32 f32x2 regs). Per node n a lane loads:
//   - D,R table values for its 8 cols (4x LDS.128, distributed across lanes)
//   - p,left for its 8 pts      (4x LDS.128, 8-way broadcast chunks)
// and performs 64 packed fma.rn.f32x2 -> 128 MACs. LDS bytes per MAC drop
// ~5x vs the broadcast kernel; FMA pipe becomes the bottleneck.

#define N_NODES   64
#define N_CLASSES 16
#define TPB       128
#define WARPS     4
#define PSTRIDE   36   // floats per p/left row (32 + pad, keeps reads conflict-free)

typedef unsigned long long u64;

__device__ float g_D[N_NODES * N_NODES];   // L - R
__device__ float g_R[N_NODES * N_NODES];   // R
__device__ float g_CP[N_NODES * N_CLASSES];
__device__ float g_dirs[N_NODES];

// ---------------------------------------------------------------------------
__global__ void fractal_setup_kernel(const float* __restrict__ dir_logits,
                                     const float* __restrict__ class_logits,
                                     const float* __restrict__ child_logits) {
    int t = threadIdx.x;
    if (t >= N_NODES) return;

    g_dirs[t] = 1.0f / (1.0f + expf(-dir_logits[t]));

    const float* lrow = child_logits + (size_t)t * 2 * N_NODES;
    const float* rrow = lrow + N_NODES;

    float Lv[N_NODES], Rv[N_NODES];
    {
        float m = -1e30f;
        for (int i = 0; i < N_NODES; i++) m = fmaxf(m, lrow[i]);
        float s = 0.0f;
        for (int i = 0; i < N_NODES; i++) s += expf(lrow[i] - m);
        float inv = 1.0f / s;
        for (int i = 0; i < N_NODES; i++) Lv[i] = expf(lrow[i] - m) * inv;
    }
    {
        float m = -1e30f;
        for (int i = 0; i < N_NODES; i++) m = fmaxf(m, rrow[i]);
        float s = 0.0f;
        for (int i = 0; i < N_NODES; i++) s += expf(rrow[i] - m);
        float inv = 1.0f / s;
        for (int i = 0; i < N_NODES; i++) Rv[i] = expf(rrow[i] - m) * inv;
    }
    for (int i = 0; i < N_NODES; i++) {
        g_D[t * N_NODES + i] = Lv[i] - Rv[i];
        g_R[t * N_NODES + i] = Rv[i];
    }
    {
        const float* crow = class_logits + t * N_CLASSES;
        float m = -1e30f;
        for (int i = 0; i < N_CLASSES; i++) m = fmaxf(m, crow[i]);
        float s = 0.0f;
        for (int i = 0; i < N_CLASSES; i++) s += expf(crow[i] - m);
        float inv = 1.0f / s;
        for (int i = 0; i < N_CLASSES; i++) g_CP[t * N_CLASSES + i] = expf(crow[i] - m) * inv;
    }
}

// Packed f32x2 helpers (Blackwell sm_103a).
#define FMA2(acc, a, b) \
    asm("fma.rn.f32x2 %0, %1, %2, %0;" : "+l"(acc) : "l"(a), "l"(b))
#define MUL2(d, a, b) \
    asm("mul.rn.f32x2 %0, %1, %2;" : "=l"(d) : "l"(a), "l"(b))
#define PACK_DUP(d, s) \
    asm("mov.b64 %0, {%1, %1};" : "=l"(d) : "f"(s))
#define UNPACK2(lo, hi, v) \
    asm("mov.b64 {%0, %1}, %2;" : "=f"(lo), "=f"(hi) : "l"(v))

__device__ __forceinline__ int decode_depth(const void* mdp) {
    int v = *reinterpret_cast<const int*>(mdp);
    if (v >= 1 && v <= 1000) return v;
    float f = __int_as_float(v);
    if (f >= 1.0f && f <= 1000.0f) return (int)f;
    return 10;
}

// Shared memory (floats):
//   Ds 4096 | Rs 4096 | CPs 1024 | SPs 64 | DIRs 64 |
//   P  WARPS*64*PSTRIDE | Lf WARPS*64*PSTRIDE
#define SMEM_FLOATS (4096 + 4096 + 1024 + 64 + 64 + 2 * WARPS * N_NODES * PSTRIDE)
#define SMEM_BYTES  (SMEM_FLOATS * 4)

__global__ __launch_bounds__(TPB, 2)
void fractal_main_kernel(const float* __restrict__ x_pos,
                         const float* __restrict__ y_pos,
                         const float* __restrict__ sp,
                         const void*  __restrict__ max_depth_ptr,
                         float* __restrict__ out,
                         int B) {
    extern __shared__ float sm[];
    float* Ds    = sm;                                    // [64][64]
    float* Rs    = Ds + 4096;                             // [64][64]
    float* CPs   = Rs + 4096;                             // [64][16]
    float* SPs   = CPs + 1024;                            // [64]
    float* DIRs  = SPs + 64;                              // [64]
    float* Pbase = DIRs + 64;                             // [WARPS][64][PSTRIDE]
    float* Lfbase = Pbase + WARPS * N_NODES * PSTRIDE;

    const int tid  = threadIdx.x;
    const int wid  = tid >> 5;
    const int lane = tid & 31;
    const int cg   = lane & 7;    // col group (8 cols: 4cg..4cg+3 and 32+4cg..+3)
    const int pg   = lane >> 3;   // point group (8 pts: 8pg..8pg+7)

    // Cooperative table load
    for (int i = tid; i < 4096; i += TPB) { Ds[i] = g_D[i]; Rs[i] = g_R[i]; }
    for (int i = tid; i < 1024; i += TPB) CPs[i] = g_CP[i];
    if (tid < N_NODES) { SPs[tid] = sp[tid]; DIRs[tid] = g_dirs[tid]; }
    __syncthreads();

    float* Pw  = Pbase  + wid * N_NODES * PSTRIDE;
    float* Lfw = Lfbase + wid * N_NODES * PSTRIDE;

    const long long warp_pt0 = (long long)blockIdx.x * TPB + wid * 32;
    const long long my_pt    = warp_pt0 + lane;
    const bool in_range = (my_pt < B);

    const int md = decode_depth(max_depth_ptr);
    const float x = in_range ? x_pos[my_pt] : 0.0f;
    const float y = in_range ? y_pos[my_pt] : 0.0f;

    // Init p and left: lane handles local point `lane` across all nodes.
    // Writes addr 36n+lane -> bank (4n+lane)%32: conflict-free per instruction.
    #pragma unroll 4
    for (int n = 0; n < N_NODES; ++n) {
        float s = SPs[n], d = DIRs[n];
        float hl = 1.0f / (1.0f + __expf(x - s));   // sigmoid(s - x)
        float vl = 1.0f / (1.0f + __expf(y - s));   // sigmoid(s - y)
        Lfw[n * PSTRIDE + lane] = (1.0f - d) * hl + d * vl;
        Pw[n * PSTRIDE + lane]  = (n == 0) ? 1.0f : 0.0f;
    }
    __syncwarp();

    // Depth loop: acc[c][q] = f32x2 over point-pairs q (8 pts), c over 8 cols.
    for (int it = 0; it < md; ++it) {
        u64 acc[8][4];
        #pragma unroll
        for (int c = 0; c < 8; c++)
            #pragma unroll
            for (int q = 0; q < 4; q++) acc[c][q] = 0ull;

        #pragma unroll 2
        for (int n = 0; n < N_NODES; ++n) {
            const float* drow = Ds + n * 64;
            const float* rrow = Rs + n * 64;
            // Distributed table loads: 8 contiguous 16B chunks across cg -> conflict-free
            ulonglong2 dlo = *reinterpret_cast<const ulonglong2*>(drow + 4 * cg);
            ulonglong2 dhi = *reinterpret_cast<const ulonglong2*>(drow + 32 + 4 * cg);
            ulonglong2 rlo = *reinterpret_cast<const ulonglong2*>(rrow + 4 * cg);
            ulonglong2 rhi = *reinterpret_cast<const ulonglong2*>(rrow + 32 + 4 * cg);

            const float* prow = Pw  + n * PSTRIDE + 8 * pg;
            const float* lrow = Lfw + n * PSTRIDE + 8 * pg;
            ulonglong2 pA = *reinterpret_cast<const ulonglong2*>(prow);
            ulonglong2 pB = *reinterpret_cast<const ulonglong2*>(prow + 4);
            ulonglong2 lA = *reinterpret_cast<const ulonglong2*>(lrow);
            ulonglong2 lB = *reinterpret_cast<const ulonglong2*>(lrow + 4);

            u64 p2[4] = { pA.x, pA.y, pB.x, pB.y };
            u64 l2[4] = { lA.x, lA.y, lB.x, lB.y };
            u64 a2[4];
            #pragma unroll
            for (int q = 0; q < 4; q++) MUL2(a2[q], p2[q], l2[q]);   // a = p*left

            // Broadcast-dup table scalars into f32x2
            float dsc[8], rsc[8];
            UNPACK2(dsc[0], dsc[1], dlo.x); UNPACK2(dsc[2], dsc[3], dlo.y);
            UNPACK2(dsc[4], dsc[5], dhi.x); UNPACK2(dsc[6], dsc[7], dhi.y);
            UNPACK2(rsc[0], rsc[1], rlo.x); UNPACK2(rsc[2], rsc[3], rlo.y);
            UNPACK2(rsc[4], rsc[5], rhi.x); UNPACK2(rsc[6], rsc[7], rhi.y);

            #pragma unroll
            for (int c = 0; c < 8; c++) {
                u64 dd, rr;
                PACK_DUP(dd, dsc[c]);
                PACK_DUP(rr, rsc[c]);
                #pragma unroll
                for (int q = 0; q < 4; q++) {
                    FMA2(acc[c][q], a2[q], dd);   // a @ (L-R)
                    FMA2(acc[c][q], p2[q], rr);   // p @ R
                }
            }
        }

        __syncwarp();   // all lanes done reading P before overwrite

        // Writeback: P[col][8pg + 2q..] = acc. STS.64, ~4-way conflict (ok).
        #pragma unroll
        for (int c = 0; c < 8; c++) {
            int col = (c < 4) ? (4 * cg + c) : (28 + 4 * cg + c);  // {4cg..}U{32+4cg..}
            u64* dst = reinterpret_cast<u64*>(Pw + col * PSTRIDE + 8 * pg);
            #pragma unroll
            for (int q = 0; q < 4; q++) dst[q] = acc[c][q];
        }
        __syncwarp();
    }

    // Final: out = (p / max(sum p, eps)) @ CP. Lane handles its own point.
    if (in_range) {
        float sum = 0.0f;
        u64 o2[8];
        #pragma unroll
        for (int k = 0; k < 8; k++) o2[k] = 0ull;

        #pragma unroll 4
        for (int n = 0; n < N_NODES; ++n) {
            float pv = Pw[n * PSTRIDE + lane];
            sum += pv;
            u64 pv2;
            PACK_DUP(pv2, pv);
            const ulonglong2* crow = reinterpret_cast<const ulonglong2*>(CPs + n * N_CLASSES);
            #pragma unroll
            for (int k = 0; k < 4; k++) {
                ulonglong2 cv = crow[k];
                FMA2(o2[2 * k],     pv2, cv.x);
                FMA2(o2[2 * k + 1], pv2, cv.y);
            }
        }

        float inv = 1.0f / fmaxf(sum, 1e-10f);
        float4* o4 = reinterpret_cast<float4*>(out + my_pt * N_CLASSES);
        #pragma unroll
        for (int k = 0; k < 4; k++) {
            float a0, a1, a2f, a3;
            UNPACK2(a0, a1, o2[2 * k]);
            UNPACK2(a2f, a3, o2[2 * k + 1]);
            float4 v;
            v.x = a0 * inv; v.y = a1 * inv; v.z = a2f * inv; v.w = a3 * inv;
            o4[k] = v;
        }
    }
}

// ---------------------------------------------------------------------------
extern "C" void kernel_launch(void* const* d_in, const int* in_sizes, int n_in,
                              void* d_out, int out_size) {
    const float* x_pos = (const float*)d_in[0];
    const float* y_pos = (const float*)d_in[1];
    const float* sp    = (const float*)d_in[2];
    const float* dirl  = (const float*)d_in[3];
    const float* cls   = (const float*)d_in[4];
    const float* child = (const float*)d_in[5];
    const void*  mdp   = d_in[6];
    float* out = (float*)d_out;

    int B = in_sizes[0];

    cudaFuncSetAttribute(fractal_main_kernel,
                         cudaFuncAttributeMaxDynamicSharedMemorySize, SMEM_BYTES);

    fractal_setup_kernel<<<1, 64>>>(dirl, cls, child);

    int grid = (B + TPB - 1) / TPB;
    fractal_main_kernel<<<grid, TPB, SMEM_BYTES>>>(x_pos, y_pos, sp, mdp, out, B);
}

// round 7
// speedup vs baseline: 1.4409x; 1.0909x over previous
#include <cuda_runtime.h>
#include <cuda_bf16.h>

// Fractal2DDiff — SIMT f32x2, register-tiled warp micro-GEMM, v3.
//  * rank-1 analytic first step: p1 = R[0,:] + left0*D[0,:]
//  * folded final step: out = (p9.left)@(D@CP) + p9@(R@CP)   (N=16)
//  * single CTA of 10 warps per SM, one shared table copy (225.8KB smem)
// L,R row-stochastic => sum(p) invariant; CP rows sum to 1 => sum of the 16
// outputs equals sum(p_final) => normalize the 16 outputs by their own sum.

#define N_NODES   64
#define N_CLASSES 16
#define WARPS     10
#define TPB       (WARPS * 32)
#define PSTRIDE   36   // floats per p/left row (32 + pad)

typedef unsigned long long u64;

__device__ float g_D[N_NODES * N_NODES];      // L - R
__device__ float g_R[N_NODES * N_NODES];      // R
__device__ float g_DC[N_NODES * N_CLASSES];   // D @ CP
__device__ float g_RC[N_NODES * N_CLASSES];   // R @ CP
__device__ float g_par[128];                  // exp(-sp) | dirs

// ---------------------------------------------------------------------------
__global__ void fractal_setup_kernel(const float* __restrict__ sp,
                                     const float* __restrict__ dir_logits,
                                     const float* __restrict__ class_logits,
                                     const float* __restrict__ child_logits) {
    __shared__ float sCP[N_NODES * N_CLASSES];
    int t = threadIdx.x;   // 64 threads, t = node

    {   // CP row t
        const float* cr = class_logits + t * N_CLASSES;
        float m = -1e30f;
        for (int i = 0; i < N_CLASSES; i++) m = fmaxf(m, cr[i]);
        float s = 0.0f;
        for (int i = 0; i < N_CLASSES; i++) s += expf(cr[i] - m);
        float inv = 1.0f / s;
        for (int i = 0; i < N_CLASSES; i++) sCP[t * N_CLASSES + i] = expf(cr[i] - m) * inv;
    }
    __syncthreads();

    const float* lr = child_logits + (size_t)t * 2 * N_NODES;
    const float* rr = lr + N_NODES;
    float Lv[64], Rv[64], Dv[64];
    {
        float m = -1e30f;
        for (int i = 0; i < 64; i++) m = fmaxf(m, lr[i]);
        float s = 0.0f;
        for (int i = 0; i < 64; i++) s += expf(lr[i] - m);
        float inv = 1.0f / s;
        for (int i = 0; i < 64; i++) Lv[i] = expf(lr[i] - m) * inv;
    }
    {
        float m = -1e30f;
        for (int i = 0; i < 64; i++) m = fmaxf(m, rr[i]);
        float s = 0.0f;
        for (int i = 0; i < 64; i++) s += expf(rr[i] - m);
        float inv = 1.0f / s;
        for (int i = 0; i < 64; i++) Rv[i] = expf(rr[i] - m) * inv;
    }
    for (int i = 0; i < 64; i++) {
        Dv[i] = Lv[i] - Rv[i];
        g_D[t * 64 + i] = Dv[i];
        g_R[t * 64 + i] = Rv[i];
    }
    // Folded final tables: DC[t][jc] = sum_j D[t][j]*CP[j][jc]
    for (int jc = 0; jc < N_CLASSES; jc++) {
        float ds = 0.0f, rs = 0.0f;
        for (int j = 0; j < 64; j++) {
            ds += Dv[j] * sCP[j * N_CLASSES + jc];
            rs += Rv[j] * sCP[j * N_CLASSES + jc];
        }
        g_DC[t * N_CLASSES + jc] = ds;
        g_RC[t * N_CLASSES + jc] = rs;
    }
    g_par[t]      = expf(-sp[t]);
    g_par[64 + t] = 1.0f / (1.0f + expf(-dir_logits[t]));
}

// Packed f32x2 helpers (sm_103a)
#define FMA2(acc, a, b) \
    asm("fma.rn.f32x2 %0, %1, %2, %0;" : "+l"(acc) : "l"(a), "l"(b))
#define MUL2(d, a, b) \
    asm("mul.rn.f32x2 %0, %1, %2;" : "=l"(d) : "l"(a), "l"(b))
#define PACK_DUP(d, s) \
    asm("mov.b64 %0, {%1, %1};" : "=l"(d) : "f"(s))
#define UNPACK2(lo, hi, v) \
    asm("mov.b64 {%0, %1}, %2;" : "=f"(lo), "=f"(hi) : "l"(v))

__device__ __forceinline__ int decode_depth(const void* mdp) {
    int v = *reinterpret_cast<const int*>(mdp);
    if (v >= 1 && v <= 1000) return v;
    float f = __int_as_float(v);
    if (f >= 1.0f && f <= 1000.0f) return (int)f;
    return 10;
}

// smem floats: Ds 4096 | Rs 4096 | DCs 1024 | RCs 1024 | PAR 128 |
//              state: WARPS * (P 2304 + Lf 2304)
#define SMEM_FLOATS (4096 + 4096 + 1024 + 1024 + 128 + WARPS * 2 * 64 * PSTRIDE)
#define SMEM_BYTES  (SMEM_FLOATS * 4)

__global__ __launch_bounds__(TPB, 1)
void fractal_main_kernel(const float* __restrict__ x_pos,
                         const float* __restrict__ y_pos,
                         const void*  __restrict__ max_depth_ptr,
                         float* __restrict__ out,
                         int B) {
    extern __shared__ float sm[];
    float* Ds  = sm;
    float* Rs  = Ds + 4096;
    float* DCs = Rs + 4096;
    float* RCs = DCs + 1024;
    float* PAR = RCs + 1024;
    float* ST  = PAR + 128;

    const int tid  = threadIdx.x;
    const int wid  = tid >> 5;
    const int lane = tid & 31;
    const int cg   = lane & 7;    // col group
    const int pg   = lane >> 3;   // point group (4 groups x 8 pts)

    for (int i = tid; i < 4096; i += TPB) { Ds[i] = g_D[i]; Rs[i] = g_R[i]; }
    for (int i = tid; i < 1024; i += TPB) { DCs[i] = g_DC[i]; RCs[i] = g_RC[i]; }
    if (tid < 128) PAR[tid] = g_par[tid];
    __syncthreads();

    float* Pw  = ST + wid * (2 * 64 * PSTRIDE);
    float* Lfw = Pw + 64 * PSTRIDE;

    const long long my_pt = (long long)blockIdx.x * TPB + wid * 32 + lane;
    const bool inr = (my_pt < B);

    int md = decode_depth(max_depth_ptr);
    if (md < 2) md = 2;
    const int full_iters = md - 2;

    const float x = inr ? x_pos[my_pt] : 0.5f;
    const float y = inr ? y_pos[my_pt] : 0.5f;
    const float ex = __expf(x), ey = __expf(y);

    // left[n] for own point (own smem column, no cross-thread hazard)
    #pragma unroll 8
    for (int n = 0; n < N_NODES; ++n) {
        float tn = PAR[n], d = PAR[64 + n];
        float hl = __fdividef(1.0f, 1.0f + ex * tn);   // sigmoid(sp-x)
        float vl = __fdividef(1.0f, 1.0f + ey * tn);   // sigmoid(sp-y)
        Lfw[n * PSTRIDE + lane] = hl + d * (vl - hl);
    }
    // rank-1 first step: p1 = R[0,:] + left0 * D[0,:]
    float l0;
    {
        float t0 = PAR[0], d0 = PAR[64];
        float hl = __fdividef(1.0f, 1.0f + ex * t0);
        float vl = __fdividef(1.0f, 1.0f + ey * t0);
        l0 = hl + d0 * (vl - hl);
    }
    #pragma unroll 8
    for (int n = 0; n < N_NODES; ++n)
        Pw[n * PSTRIDE + lane] = fmaf(l0, Ds[n], Rs[n]);   // rows 0 of D,R
    __syncwarp();

    // ------- full iterations: acc[c][q], c=8 cols, q=4 point-pairs -------
    for (int it = 0; it < full_iters; ++it) {
        u64 acc[8][4];
        #pragma unroll
        for (int c = 0; c < 8; c++)
            #pragma unroll
            for (int q = 0; q < 4; q++) acc[c][q] = 0ull;

        #pragma unroll 2
        for (int n = 0; n < N_NODES; ++n) {
            const float* drow = Ds + n * 64;
            const float* rrow = Rs + n * 64;
            ulonglong2 dlo = *reinterpret_cast<const ulonglong2*>(drow + 4 * cg);
            ulonglong2 dhi = *reinterpret_cast<const ulonglong2*>(drow + 32 + 4 * cg);
            ulonglong2 rlo = *reinterpret_cast<const ulonglong2*>(rrow + 4 * cg);
            ulonglong2 rhi = *reinterpret_cast<const ulonglong2*>(rrow + 32 + 4 * cg);

            const float* prow = Pw  + n * PSTRIDE + 8 * pg;
            const float* lrow = Lfw + n * PSTRIDE + 8 * pg;
            ulonglong2 pA = *reinterpret_cast<const ulonglong2*>(prow);
            ulonglong2 pB = *reinterpret_cast<const ulonglong2*>(prow + 4);
            ulonglong2 lA = *reinterpret_cast<const ulonglong2*>(lrow);
            ulonglong2 lB = *reinterpret_cast<const ulonglong2*>(lrow + 4);

            u64 p2[4] = { pA.x, pA.y, pB.x, pB.y };
            u64 l2[4] = { lA.x, lA.y, lB.x, lB.y };
            u64 a2[4];
            #pragma unroll
            for (int q = 0; q < 4; q++) MUL2(a2[q], p2[q], l2[q]);

            float dsc[8], rsc[8];
            UNPACK2(dsc[0], dsc[1], dlo.x); UNPACK2(dsc[2], dsc[3], dlo.y);
            UNPACK2(dsc[4], dsc[5], dhi.x); UNPACK2(dsc[6], dsc[7], dhi.y);
            UNPACK2(rsc[0], rsc[1], rlo.x); UNPACK2(rsc[2], rsc[3], rlo.y);
            UNPACK2(rsc[4], rsc[5], rhi.x); UNPACK2(rsc[6], rsc[7], rhi.y);

            #pragma unroll
            for (int c = 0; c < 8; c++) {
                u64 dd, rr;
                PACK_DUP(dd, dsc[c]);
                PACK_DUP(rr, rsc[c]);
                #pragma unroll
                for (int q = 0; q < 4; q++) {
                    FMA2(acc[c][q], a2[q], dd);
                    FMA2(acc[c][q], p2[q], rr);
                }
            }
        }

        __syncwarp();
        #pragma unroll
        for (int c = 0; c < 8; c++) {
            int col = (c < 4) ? (4 * cg + c) : (28 + 4 * cg + c);
            u64* dst = reinterpret_cast<u64*>(Pw + col * PSTRIDE + 8 * pg);
            #pragma unroll
            for (int q = 0; q < 4; q++) dst[q] = acc[c][q];
        }
        __syncwarp();
    }

    // ------- folded final step: 16 classes, lane tile 8 pts x 2 classes -------
    {
        u64 fac[2][4];
        #pragma unroll
        for (int ci = 0; ci < 2; ci++)
            #pragma unroll
            for (int q = 0; q < 4; q++) fac[ci][q] = 0ull;

        #pragma unroll 2
        for (int n = 0; n < N_NODES; ++n) {
            u64 dpair = *reinterpret_cast<const u64*>(DCs + n * N_CLASSES + 2 * cg);
            u64 rpair = *reinterpret_cast<const u64*>(RCs + n * N_CLASSES + 2 * cg);
            float dc0, dc1, rc0, rc1;
            UNPACK2(dc0, dc1, dpair);
            UNPACK2(rc0, rc1, rpair);

            const float* prow = Pw  + n * PSTRIDE + 8 * pg;
            const float* lrow = Lfw + n * PSTRIDE + 8 * pg;
            ulonglong2 pA = *reinterpret_cast<const ulonglong2*>(prow);
            ulonglong2 pB = *reinterpret_cast<const ulonglong2*>(prow + 4);
            ulonglong2 lA = *reinterpret_cast<const ulonglong2*>(lrow);
            ulonglong2 lB = *reinterpret_cast<const ulonglong2*>(lrow + 4);

            u64 p2[4] = { pA.x, pA.y, pB.x, pB.y };
            u64 l2[4] = { lA.x, lA.y, lB.x, lB.y };
            u64 a2[4];
            #pragma unroll
            for (int q = 0; q < 4; q++) MUL2(a2[q], p2[q], l2[q]);

            u64 dd0, dd1, rr0, rr1;
            PACK_DUP(dd0, dc0); PACK_DUP(dd1, dc1);
            PACK_DUP(rr0, rc0); PACK_DUP(rr1, rc1);
            #pragma unroll
            for (int q = 0; q < 4; q++) {
                FMA2(fac[0][q], a2[q], dd0);
                FMA2(fac[0][q], p2[q], rr0);
                FMA2(fac[1][q], a2[q], dd1);
                FMA2(fac[1][q], p2[q], rr1);
            }
        }

        __syncwarp();
        // park class outputs in P rows 0..15 (state is dead now)
        #pragma unroll
        for (int ci = 0; ci < 2; ci++) {
            int cls = 2 * cg + ci;
            u64* dst = reinterpret_cast<u64*>(Pw + cls * PSTRIDE + 8 * pg);
            #pragma unroll
            for (int q = 0; q < 4; q++) dst[q] = fac[ci][q];
        }
        __syncwarp();
    }

    // ------- gather own point, normalize, store -------
    if (inr) {
        float o[16], s = 0.0f;
        #pragma unroll
        for (int c = 0; c < 16; c++) { o[c] = Pw[c * PSTRIDE + lane]; s += o[c]; }
        float inv = 1.0f / fmaxf(s, 1e-10f);
        float4* o4 = reinterpret_cast<float4*>(out + my_pt * N_CLASSES);
        #pragma unroll
        for (int k = 0; k < 4; k++) {
            float4 v;
            v.x = o[4 * k] * inv;     v.y = o[4 * k + 1] * inv;
            v.z = o[4 * k + 2] * inv; v.w = o[4 * k + 3] * inv;
            o4[k] = v;
        }
    }
}

// ---------------------------------------------------------------------------
extern "C" void kernel_launch(void* const* d_in, const int* in_sizes, int n_in,
                              void* d_out, int out_size) {
    const float* x_pos = (const float*)d_in[0];
    const float* y_pos = (const float*)d_in[1];
    const float* sp    = (const float*)d_in[2];
    const float* dirl  = (const float*)d_in[3];
    const float* cls   = (const float*)d_in[4];
    const float* child = (const float*)d_in[5];
    const void*  mdp   = d_in[6];
    float* out = (float*)d_out;

    int B = in_sizes[0];

    cudaFuncSetAttribute(fractal_main_kernel,
                         cudaFuncAttributeMaxDynamicSharedMemorySize, SMEM_BYTES);

    fractal_setup_kernel<<<1, 64>>>(sp, dirl, cls, child);

    int grid = (B + TPB - 1) / TPB;
    fractal_main_kernel<<<grid, TPB, SMEM_BYTES>>>(x_pos, y_pos, mdp, out, B);
}